// round 9
// baseline (speedup 1.0000x reference)
#include <cuda_runtime.h>
#include <cstddef>

// PCEN transform:
//   m_t = (1-S)*m_{t-1} + S*x_t   (EMA over time axis, per [b,f] row)
//   out = (x / (m+EPS)^ALPHA + DELTA)^R - DELTA^R,  R = 0.5
//
// Layout: x is [32, 256, 4096] fp32, time (4096) contiguous.
// Strategy: one warp per row. Each lane owns 4 consecutive elements (float4).
// The EMA is an affine recurrence with uniform decay, so a Hillis-Steele
// warp scan with precomputed decay powers composes lane segments exactly.

#define S_CONST     0.025f
#define C_CONST     0.975f
#define EPS_CONST   1e-6f
#define ALPHA_CONST 0.98f
#define DELTA_CONST 2.0f
#define SQRT_DELTA  1.41421356237309515f   // sqrt(2)

#define T_LEN   4096
#define CHUNK   128          // elements per warp-chunk (32 lanes x 4)
#define NCHUNK  (T_LEN / CHUNK)
#define WARPS_PER_BLOCK 8
#define BLOCK_THREADS   (WARPS_PER_BLOCK * 32)

// Raw MUFU ops via PTX — guaranteed single-instruction EX2/LG2 regardless of
// compile flags (note: __exp2f is NOT a device intrinsic; this is).
__device__ __forceinline__ float ex2_approx(float a) {
    float r;
    asm("ex2.approx.f32 %0, %1;" : "=f"(r) : "f"(a));
    return r;
}
__device__ __forceinline__ float lg2_approx(float a) {
    float r;
    asm("lg2.approx.f32 %0, %1;" : "=f"(r) : "f"(a));
    return r;
}

// fused epilogue: (x * (m+eps)^-alpha + delta)^0.5 - delta^0.5
__device__ __forceinline__ float pcen_epilogue(float xv, float m) {
    float p = ex2_approx(-ALPHA_CONST * lg2_approx(m + EPS_CONST));
    return __fsqrt_rn(fmaf(xv, p, DELTA_CONST)) - SQRT_DELTA;
}

__global__ __launch_bounds__(BLOCK_THREADS, 8)
void pcen_kernel(const float* __restrict__ x, float* __restrict__ out, int nrows)
{
    const int gwarp = (blockIdx.x * BLOCK_THREADS + threadIdx.x) >> 5;
    const int lane  = threadIdx.x & 31;
    if (gwarp >= nrows) return;

    const float* xr  = x   + (size_t)gwarp * T_LEN;
    float*       orw = out + (size_t)gwarp * T_LEN;

    // Decay powers (compile-time folds for all but clane)
    const float c4   = C_CONST * C_CONST * C_CONST * C_CONST; // c^4
    const float f1   = c4;          // c^4
    const float f2   = f1 * f1;     // c^8
    const float f3   = f2 * f2;     // c^16
    const float f4   = f3 * f3;     // c^32
    const float f5   = f4 * f4;     // c^64
    const float c128 = f5 * f5;     // c^128
    // c^(4*lane) via MUFU: 2^(4*lane*log2(c))
    const float clane = ex2_approx(4.0f * (float)lane * lg2_approx(C_CONST));

    float carry = 0.0f;

    // Prefetch chunk 0
    float4 xv = reinterpret_cast<const float4*>(xr)[lane];

    #pragma unroll 1
    for (int ch = 0; ch < NCHUNK; ++ch) {
        // Prefetch next chunk while we scan the current one
        float4 nxt = xv;
        if (ch + 1 < NCHUNK)
            nxt = reinterpret_cast<const float4*>(xr + (ch + 1) * CHUNK)[lane];

        // ---- local EMA of this lane's 4 elements, zero-initialized ----
        float b;
        b = S_CONST * xv.x;
        b = fmaf(C_CONST, b, S_CONST * xv.y);
        b = fmaf(C_CONST, b, S_CONST * xv.z);
        b = fmaf(C_CONST, b, S_CONST * xv.w);

        // ---- inclusive affine warp scan: v_l = b_l + c^4 b_{l-1} + ... ----
        float v = b, u;
        u = __shfl_up_sync(0xffffffffu, v, 1);  if (lane >= 1)  v = fmaf(f1, u, v);
        u = __shfl_up_sync(0xffffffffu, v, 2);  if (lane >= 2)  v = fmaf(f2, u, v);
        u = __shfl_up_sync(0xffffffffu, v, 4);  if (lane >= 4)  v = fmaf(f3, u, v);
        u = __shfl_up_sync(0xffffffffu, v, 8);  if (lane >= 8)  v = fmaf(f4, u, v);
        u = __shfl_up_sync(0xffffffffu, v, 16); if (lane >= 16) v = fmaf(f5, u, v);

        // exclusive prefix (m at end of previous lane's segment, chunk-local)
        float excl = __shfl_up_sync(0xffffffffu, v, 1);
        if (lane == 0) excl = 0.0f;

        // fold in the cross-chunk carry: true m entering this lane's segment
        float m = fmaf(clane, carry, excl);

        // carry for next chunk (broadcast lane 31's inclusive value)
        float v31 = __shfl_sync(0xffffffffu, v, 31);
        carry = fmaf(c128, carry, v31);

        // ---- reconstruct the 4 EMA values + fused PCEN epilogue ----
        float4 ov;
        m = fmaf(C_CONST, m, S_CONST * xv.x);
        ov.x = pcen_epilogue(xv.x, m);
        m = fmaf(C_CONST, m, S_CONST * xv.y);
        ov.y = pcen_epilogue(xv.y, m);
        m = fmaf(C_CONST, m, S_CONST * xv.z);
        ov.z = pcen_epilogue(xv.z, m);
        m = fmaf(C_CONST, m, S_CONST * xv.w);
        ov.w = pcen_epilogue(xv.w, m);

        reinterpret_cast<float4*>(orw + ch * CHUNK)[lane] = ov;

        xv = nxt;
    }
}

extern "C" void kernel_launch(void* const* d_in, const int* in_sizes, int n_in,
                              void* d_out, int out_size)
{
    const float* x = (const float*)d_in[0];
    float* out = (float*)d_out;

    int nrows = in_sizes[0] / T_LEN;                    // 32*256 = 8192
    int blocks = (nrows + WARPS_PER_BLOCK - 1) / WARPS_PER_BLOCK;  // 1024

    pcen_kernel<<<blocks, BLOCK_THREADS>>>(x, out, nrows);
}